// round 7
// baseline (speedup 1.0000x reference)
#include <cuda_runtime.h>

#define T     4096
#define TQ    1024        // float4s per array
#define NTH   160
#define C     16
#define W2    146         // pair-row width (64-bit units)
#define BUFP  (8 * W2)    // 1168 pairs per buffer
#define NSTG  528         // float4s staged per array (pairs 0..1055)

typedef unsigned long long u64;

// db4 synthesis filters pre-scaled by 0.5 (the per-level factor)
#define L0c ( 0.5f *  0.23037781330885523f)
#define L1c ( 0.5f *  0.7148465705525415f)
#define L2c ( 0.5f *  0.6308807679295904f)
#define L3c ( 0.5f * -0.02798376941698385f)
#define L4c ( 0.5f * -0.18703481171888114f)
#define L5c ( 0.5f *  0.030841381835986965f)
#define L6c ( 0.5f *  0.032883011666982945f)
#define L7c ( 0.5f * -0.010597401784997278f)
// rec_hi[k] = (-1)^k * rec_lo[7-k]  ->  even k: +L[7-k], odd k: -L[7-k]
#define H0c ( L7c)
#define H1c (-L6c)
#define H2c ( L5c)
#define H3c (-L4c)
#define H4c ( L3c)
#define H5c (-L2c)
#define H6c ( L1c)
#define H7c (-L0c)

// Packed (x == y) coefficient pairs for FFMA2, loaded as LDC.64 (no movs)
__constant__ float2 CL2[8] = {
    {L0c,L0c},{L1c,L1c},{L2c,L2c},{L3c,L3c},{L4c,L4c},{L5c,L5c},{L6c,L6c},{L7c,L7c}};
__constant__ float2 CH2[8] = {
    {H0c,H0c},{H1c,H1c},{H2c,H2c},{H3c,H3c},{H4c,H4c},{H5c,H5c},{H6c,H6c},{H7c,H7c}};

__device__ __forceinline__ void fma2(u64& d, u64 c, u64 v) {
    asm("fma.rn.f32x2 %0, %1, %2, %0;" : "+l"(d) : "l"(c), "l"(v));
}

// Stage one array: global float4s -> pair-transposed shared.
// Pair p at phys64 = (p & 7)*W2 + (p >> 3).  float4 idx -> pairs 2idx, 2idx+1.
__device__ __forceinline__ void stage(u64* __restrict__ s,
                                      const float4* __restrict__ g4,
                                      int f4base, int tid) {
#pragma unroll
    for (int i = 0; i < 4; ++i) {
        int idx = tid + i * NTH;
        if (idx < NSTG) {
            float4 v = __ldg(&g4[(f4base + idx) & (TQ - 1)]);
            int r = 2 * (idx & 3);
            int q = idx >> 2;
            *(float2*)(s + (r + 0) * W2 + q) = make_float2(v.x, v.y);
            *(float2*)(s + (r + 1) * W2 + q) = make_float2(v.z, v.w);
        }
    }
}

// Even-dilation pass (all tap shifts even): stream aligned pairs q = 0..QMAX.
// acc pair kk gets tap m from pair q = kk + (D*(3-m)+OFF)/2.
template <int D, int OFF, int QMAX>
__device__ __forceinline__ void pass_even(const u64* __restrict__ buf, u64* acc,
                                          const float2* __restrict__ coef, int t) {
    u64 c[8];
    const u64* cu = (const u64*)coef;          // LDC.64, no register packing
#pragma unroll
    for (int m = 0; m < 8; ++m) c[m] = cu[m];
    const u64* p = buf + t;
#pragma unroll
    for (int q = 0; q <= QMAX; ++q) {
        u64 v = p[(q & 7) * W2 + (q >> 3)];
#pragma unroll
        for (int m = 0; m < 8; ++m) {
            const int kk = q - (D * (3 - m) + OFF) / 2;
            if (kk >= 0 && kk < 8) fma2(acc[kk], c[m], v);
        }
    }
}

// D=1 scalar pass (OFF=8): acc[j] += coef[m] * buf[li], li = j + 11 - m.
// Stream pairs q=2..13 (li = 2q, 2q+1); halves consumed directly, FFMA-imm.
__device__ __forceinline__ void pass_d1(const u64* __restrict__ buf,
                                        float* acc, const float* cf, int t) {
    const u64* p = buf + t;
#pragma unroll
    for (int q = 2; q <= 13; ++q) {
        u64 vv = p[(q & 7) * W2 + (q >> 3)];
        float2 v = *(float2*)&vv;
#pragma unroll
        for (int m = 0; m < 8; ++m) {
            {   // li = 2q   -> j = 2q - 11 + m
                const int j = 2 * q - 11 + m;
                if (j >= 0 && j < C) acc[j] = fmaf(cf[m], v.x, acc[j]);
            }
            {   // li = 2q+1 -> j = 2q - 10 + m
                const int j = 2 * q - 10 + m;
                if (j >= 0 && j < C) acc[j] = fmaf(cf[m], v.y, acc[j]);
            }
        }
    }
}

__global__ void __launch_bounds__(NTH, 6)
iswt_kernel(const float* __restrict__ x, float* __restrict__ out) {
    __shared__ u64 sA[BUFP];   // cA3, then cD1
    __shared__ u64 sB[BUFP];   // cD3, then R2
    __shared__ u64 sC[BUFP];   // cD2
    __shared__ u64 sD[BUFP];   // R1

    const int bn  = blockIdx.x >> 1;          // row in [0, 2048)
    const int S   = (blockIdx.x & 1) << 11;   // chunk start: 0 or 2048
    const int tid = threadIdx.x;
    const float* g = x + (size_t)bn * 4 * T;  // cA3 | cD3 | cD2 | cD1
    const float4* g4 = (const float4*)g;

    const int o32 = (S - 32) >> 2;            // staging origins (float4 index)
    const int o16 = (S - 16) >> 2;
    const int o8  = (S - 8)  >> 2;

    stage(sA, g4 + 0 * TQ, o32, tid);         // cA3  (origin S-32)
    stage(sB, g4 + 1 * TQ, o32, tid);         // cD3  (origin S-32)
    stage(sC, g4 + 2 * TQ, o16, tid);         // cD2  (origin S-16)
    __syncthreads();

    // Level 1 (d=4, OFF=16): produce R1 (origin S-16), pairs 8t..8t+7 -> sD
    if (tid < 130) {
        u64 acc[8];
#pragma unroll
        for (int k = 0; k < 8; ++k) acc[k] = 0ULL;
        pass_even<4, 16, 21>(sA, acc, CL2, tid);
        pass_even<4, 16, 21>(sB, acc, CH2, tid);
        u64* p = sD + tid;
#pragma unroll
        for (int k = 0; k < 8; ++k) p[k * W2] = acc[k];
    }
    __syncthreads();

    // cA3 dead -> stage cD1 (origin S-8) into sA; overlaps level-2 compute
    stage(sA, g4 + 3 * TQ, o8, tid);

    // Level 2 (d=2, OFF=8): R1 + cD2 -> R2 (origin S-8) into sB (cD3 dead)
    if (tid < 129) {
        u64 acc[8];
#pragma unroll
        for (int k = 0; k < 8; ++k) acc[k] = 0ULL;
        pass_even<2, 8, 14>(sD, acc, CL2, tid);
        pass_even<2, 8, 14>(sC, acc, CH2, tid);
        u64* p = sB + tid;
#pragma unroll
        for (int k = 0; k < 8; ++k) p[k * W2] = acc[k];
    }
    __syncthreads();

    // Level 3 (d=1, OFF=8): R2 + cD1 -> global, scalar FFMA-imm
    if (tid < 128) {
        const float CFL[8] = {L0c,L1c,L2c,L3c,L4c,L5c,L6c,L7c};
        const float CFH[8] = {H0c,H1c,H2c,H3c,H4c,H5c,H6c,H7c};
        float acc[C];
#pragma unroll
        for (int j = 0; j < C; ++j) acc[j] = 0.0f;
        pass_d1(sB, acc, CFL, tid);
        pass_d1(sA, acc, CFH, tid);
        float4* o = (float4*)(out + (size_t)bn * T + S + tid * C);
#pragma unroll
        for (int q = 0; q < 4; ++q)
            o[q] = make_float4(acc[4 * q + 0], acc[4 * q + 1],
                               acc[4 * q + 2], acc[4 * q + 3]);
    }
}

extern "C" void kernel_launch(void* const* d_in, const int* in_sizes, int n_in,
                              void* d_out, int out_size) {
    const float* x = (const float*)d_in[0];
    float* out = (float*)d_out;
    iswt_kernel<<<4096, NTH>>>(x, out);
}